// round 9
// baseline (speedup 1.0000x reference)
#include <cuda_runtime.h>

// Detail loss, simplified:
//   D = sum_c (infer - ref)   per image plane
//   out = (sum|D[w+1]-D[w-1]| + sum|D[h+1]-D[h-1]|) * 0.25 / (98*258*256)
// Warp-per-(16-row x 128-col) tile: each lane owns 4 columns (1 float4 per
// plane per row), one-row-ahead software pipeline, no smem/barriers in the
// hot loop. 3136 warps fit in ONE wave at 22 warps/SM (regs capped at 93).
// The seam column between the two half-row warps is fetched with uniform
// scalar loads (single 32B sector, L2-resident).

#define NIMG   98            // 2*7*7
#define IMG_H  256
#define IMG_W  256
#define RSTRIP 16            // rows per warp tile
#define VSTRIPS (IMG_H / RSTRIP)         // 16
#define HALVES  2                        // 128-col halves
#define NWARPS (NIMG * VSTRIPS * HALVES) // 3136
#define WPB    2
#define NBLOCKS (NWARPS / WPB)           // 1568
#define PLANE  (IMG_H * IMG_W)

__device__ float        g_partials[NWARPS];
__device__ unsigned int g_count;     // zero-init; reset each launch by last block

struct Raw {
    float4 a[3], b[3];   // 3 channels x (infer, ref), 4 cols per lane
    float  sa[3], sb[3]; // seam scalars (uniform address across lanes)
};

__device__ __forceinline__ void issue_load(const float* __restrict__ pi,
                                           const float* __restrict__ pr,
                                           int row, int colbase, int seamcol,
                                           bool valid, Raw& r) {
    if (valid) {
        const size_t off  = (size_t)row * IMG_W + colbase;
        const size_t soff = (size_t)row * IMG_W + seamcol;
        #pragma unroll
        for (int c = 0; c < 3; c++) {
            r.a[c]  = *(const float4*)(pi + (size_t)c * PLANE + off);
            r.b[c]  = *(const float4*)(pr + (size_t)c * PLANE + off);
            r.sa[c] = pi[(size_t)c * PLANE + soff];
            r.sb[c] = pr[(size_t)c * PLANE + soff];
        }
    } else {
        const float4 z = make_float4(0.f, 0.f, 0.f, 0.f);
        #pragma unroll
        for (int c = 0; c < 3; c++) { r.a[c] = z; r.b[c] = z; r.sa[c] = 0.f; r.sb[c] = 0.f; }
    }
}

__device__ __forceinline__ void combine(const Raw& r, float d[4], float& ds) {
    #pragma unroll
    for (int j = 0; j < 4; j++) d[j] = 0.f;
    ds = 0.f;
    #pragma unroll
    for (int c = 0; c < 3; c++) {
        d[0] += r.a[c].x - r.b[c].x;
        d[1] += r.a[c].y - r.b[c].y;
        d[2] += r.a[c].z - r.b[c].z;
        d[3] += r.a[c].w - r.b[c].w;
        ds   += r.sa[c]  - r.sb[c];
    }
}

__global__ void __launch_bounds__(WPB * 32, 11)
detail_kernel(const float* __restrict__ infer, const float* __restrict__ ref,
              float* __restrict__ out) {
    const int tid  = threadIdx.x;
    const int lane = tid & 31;
    const int gw   = blockIdx.x * WPB + (tid >> 5);   // global warp id
    const int n    = gw >> 5;                          // / (VSTRIPS*HALVES)
    const int rem  = gw & 31;
    const int strip = rem >> 1;
    const int half  = rem & 1;
    const int r0    = strip * RSTRIP;
    const int col0  = half * 128;                      // warp's 128-col chunk
    const int colbase = col0 + lane * 4;
    const int seamcol = half ? 127 : 128;              // neighbor-half column

    const float* pi = infer + (size_t)n * 3 * PLANE;
    const float* pr = ref   + (size_t)n * 3 * PLANE;

    // Prologue: rows r0-1, r0 combined immediately; row r0+1 left in flight.
    Raw buf[2], rtop, rcur;
    issue_load(pi, pr, r0 - 1, colbase, seamcol, r0 > 0, rtop);
    issue_load(pi, pr, r0,     colbase, seamcol, true,   rcur);
    issue_load(pi, pr, r0 + 1, colbase, seamcol, true,   buf[1]);   // for h=0

    float pm[4], pc[4], pn[4];
    float es_d;                 // dummy seam for pm row
    float es_c, es_n;
    combine(rtop, pm, es_d);
    combine(rcur, pc, es_c);

    float sum = 0.f;

    #pragma unroll 2
    for (int h = 0; h < RSTRIP; h++) {
        const int g = r0 + h;
        // Issue loads for row g+2 BEFORE consuming row g+1 (one-ahead pipeline).
        issue_load(pi, pr, g + 2, colbase, seamcol,
                   (g + 2) < IMG_H && h + 1 < RSTRIP, buf[h & 1]);

        combine(buf[(h + 1) & 1], pn, es_n);   // row g+1, issued last iteration

        // Horizontal gradient on row g (values in pc; 4 cols per lane).
        float l = __shfl_up_sync(0xffffffffu,  pc[3], 1);
        float r = __shfl_down_sync(0xffffffffu, pc[0], 1);
        if (lane == 0)  l = half ? es_c : 0.f;   // seam D[127] or image edge
        if (lane == 31) r = half ? 0.f  : es_c;  // image edge or seam D[128]
        sum += fabsf(pc[1] - l);
        sum += fabsf(pc[2] - pc[0]);
        sum += fabsf(pc[3] - pc[1]);
        sum += fabsf(r - pc[2]);

        // Vertical gradient on row g.
        #pragma unroll
        for (int j = 0; j < 4; j++) sum += fabsf(pn[j] - pm[j]);

        // Roll the window.
        #pragma unroll
        for (int j = 0; j < 4; j++) { pm[j] = pc[j]; pc[j] = pn[j]; }
        es_c = es_n;
    }

    // Warp reduction.
    #pragma unroll
    for (int off = 16; off > 0; off >>= 1)
        sum += __shfl_down_sync(0xffffffffu, sum, off);

    __shared__ bool is_last;
    if (lane == 0) {
        g_partials[gw] = sum;
        __threadfence();
    }
    __syncthreads();
    if (tid == 0)
        is_last = (atomicAdd(&g_count, 1u) == NBLOCKS - 1);
    __syncthreads();

    if (is_last) {
        float t = 0.f;
        for (int i = tid; i < NWARPS; i += WPB * 32)
            t += __ldcg(&g_partials[i]);
        #pragma unroll
        for (int off = 16; off > 0; off >>= 1)
            t += __shfl_down_sync(0xffffffffu, t, off);
        __shared__ float wsum[WPB];
        if (lane == 0) wsum[tid >> 5] = t;
        __syncthreads();
        if (tid == 0) {
            float u = 0.f;
            #pragma unroll
            for (int i = 0; i < WPB; i++) u += wsum[i];
            // 0.5 (gradient coeff) * 0.5 (avg of two losses) / (98*258*256)
            out[0] = u * (0.25f / 6472704.0f);
            g_count = 0;   // deterministic across graph replays
        }
    }
}

extern "C" void kernel_launch(void* const* d_in, const int* in_sizes, int n_in,
                              void* d_out, int out_size) {
    const float* infer = (const float*)d_in[0];
    const float* ref   = (const float*)d_in[1];
    detail_kernel<<<NBLOCKS, WPB * 32>>>(infer, ref, (float*)d_out);
}

// round 10
// speedup vs baseline: 1.0067x; 1.0067x over previous
#include <cuda_runtime.h>

// Detail loss, simplified:
//   D = sum_c (infer - ref)   per image plane
//   out = (sum|D[w+1]-D[w-1]| + sum|D[h+1]-D[h-1]|) * 0.25 / (98*258*256)
// Warp-per-(16-row x 128-col) tile, one-row-ahead pipeline, no smem/barriers
// in the hot loop, single wave (3136 warps @ <=~25 warps/SM).
// SERPENTINE: odd strips walk bottom->top so halo rows shared between
// vertically adjacent strips are read at the same time -> L2 hits instead of
// DRAM re-reads (the memory subsystem is saturated; bytes are the bottleneck).

#define NIMG   98            // 2*7*7
#define IMG_H  256
#define IMG_W  256
#define RSTRIP 16            // rows per warp tile
#define VSTRIPS (IMG_H / RSTRIP)         // 16
#define HALVES  2                        // 128-col halves
#define NWARPS (NIMG * VSTRIPS * HALVES) // 3136
#define WPB    2
#define NBLOCKS (NWARPS / WPB)           // 1568
#define PLANE  (IMG_H * IMG_W)

__device__ float        g_partials[NWARPS];
__device__ unsigned int g_count;     // zero-init; reset each launch by last block

struct Raw {
    float4 a[3], b[3];   // 3 channels x (infer, ref), 4 cols per lane
    float  sa[3], sb[3]; // seam scalars (uniform address across lanes)
};

__device__ __forceinline__ void issue_load(const float* __restrict__ pi,
                                           const float* __restrict__ pr,
                                           int row, int colbase, int seamcol,
                                           bool valid, Raw& r) {
    if (valid) {
        const size_t off  = (size_t)row * IMG_W + colbase;
        const size_t soff = (size_t)row * IMG_W + seamcol;
        #pragma unroll
        for (int c = 0; c < 3; c++) {
            r.a[c]  = *(const float4*)(pi + (size_t)c * PLANE + off);
            r.b[c]  = *(const float4*)(pr + (size_t)c * PLANE + off);
            r.sa[c] = pi[(size_t)c * PLANE + soff];
            r.sb[c] = pr[(size_t)c * PLANE + soff];
        }
    } else {
        const float4 z = make_float4(0.f, 0.f, 0.f, 0.f);
        #pragma unroll
        for (int c = 0; c < 3; c++) { r.a[c] = z; r.b[c] = z; r.sa[c] = 0.f; r.sb[c] = 0.f; }
    }
}

__device__ __forceinline__ void combine(const Raw& r, float d[4], float& ds) {
    #pragma unroll
    for (int j = 0; j < 4; j++) d[j] = 0.f;
    ds = 0.f;
    #pragma unroll
    for (int c = 0; c < 3; c++) {
        d[0] += r.a[c].x - r.b[c].x;
        d[1] += r.a[c].y - r.b[c].y;
        d[2] += r.a[c].z - r.b[c].z;
        d[3] += r.a[c].w - r.b[c].w;
        ds   += r.sa[c]  - r.sb[c];
    }
}

__global__ void __launch_bounds__(WPB * 32, 11)
detail_kernel(const float* __restrict__ infer, const float* __restrict__ ref,
              float* __restrict__ out) {
    const int tid  = threadIdx.x;
    const int lane = tid & 31;
    const int gw   = blockIdx.x * WPB + (tid >> 5);   // global warp id
    const int n    = gw >> 5;                          // / (VSTRIPS*HALVES)
    const int rem  = gw & 31;
    const int strip = rem >> 1;
    const int half  = rem & 1;
    const int r0    = strip * RSTRIP;
    const int colbase = half * 128 + lane * 4;
    const int seamcol = half ? 127 : 128;              // neighbor-half column

    // Serpentine: even strips walk top->bottom, odd strips bottom->top so
    // boundary rows are touched by both neighbors at the same time (L2 hit).
    const int dir    = (strip & 1) ? -1 : 1;
    const int gstart = (strip & 1) ? (r0 + RSTRIP - 1) : r0;

    const float* pi = infer + (size_t)n * 3 * PLANE;
    const float* pr = ref   + (size_t)n * 3 * PLANE;

    // Prologue: rows gstart-dir, gstart combined now; row gstart+dir in flight.
    Raw buf[2], rtop, rcur;
    {
        const int rA = gstart - dir;
        issue_load(pi, pr, rA, colbase, seamcol, (unsigned)rA < IMG_H, rtop);
    }
    issue_load(pi, pr, gstart,       colbase, seamcol, true, rcur);
    issue_load(pi, pr, gstart + dir, colbase, seamcol, true, buf[1]);  // h=0

    float pm[4], pc[4], pn[4];       // rows g-dir, g, g+dir
    float es_d, es_c, es_n;
    combine(rtop, pm, es_d);
    combine(rcur, pc, es_c);

    float sum = 0.f;

    #pragma unroll 2
    for (int h = 0; h < RSTRIP; h++) {
        const int g = gstart + h * dir;
        // Issue loads for row g+2*dir BEFORE consuming row g+dir.
        const int rnext = g + 2 * dir;
        issue_load(pi, pr, rnext, colbase, seamcol,
                   (unsigned)rnext < IMG_H && (h + 1) < RSTRIP, buf[h & 1]);

        combine(buf[(h + 1) & 1], pn, es_n);   // row g+dir, issued last iter

        // Horizontal gradient on row g (values in pc; 4 cols per lane).
        float l = __shfl_up_sync(0xffffffffu,  pc[3], 1);
        float r = __shfl_down_sync(0xffffffffu, pc[0], 1);
        if (lane == 0)  l = half ? es_c : 0.f;   // seam D[127] or image edge
        if (lane == 31) r = half ? 0.f  : es_c;  // image edge or seam D[128]
        sum += fabsf(pc[1] - l);
        sum += fabsf(pc[2] - pc[0]);
        sum += fabsf(pc[3] - pc[1]);
        sum += fabsf(r - pc[2]);

        // Vertical gradient: |D[g+1]-D[g-1]| = |pn-pm| for either direction.
        #pragma unroll
        for (int j = 0; j < 4; j++) sum += fabsf(pn[j] - pm[j]);

        // Roll the window.
        #pragma unroll
        for (int j = 0; j < 4; j++) { pm[j] = pc[j]; pc[j] = pn[j]; }
        es_c = es_n;
    }

    // Warp reduction.
    #pragma unroll
    for (int off = 16; off > 0; off >>= 1)
        sum += __shfl_down_sync(0xffffffffu, sum, off);

    __shared__ bool is_last;
    if (lane == 0) {
        g_partials[gw] = sum;
        __threadfence();
    }
    __syncthreads();
    if (tid == 0)
        is_last = (atomicAdd(&g_count, 1u) == NBLOCKS - 1);
    __syncthreads();

    if (is_last) {
        float t = 0.f;
        for (int i = tid; i < NWARPS; i += WPB * 32)
            t += __ldcg(&g_partials[i]);
        #pragma unroll
        for (int off = 16; off > 0; off >>= 1)
            t += __shfl_down_sync(0xffffffffu, t, off);
        __shared__ float wsum[WPB];
        if (lane == 0) wsum[tid >> 5] = t;
        __syncthreads();
        if (tid == 0) {
            float u = 0.f;
            #pragma unroll
            for (int i = 0; i < WPB; i++) u += wsum[i];
            // 0.5 (gradient coeff) * 0.5 (avg of two losses) / (98*258*256)
            out[0] = u * (0.25f / 6472704.0f);
            g_count = 0;   // deterministic across graph replays
        }
    }
}

extern "C" void kernel_launch(void* const* d_in, const int* in_sizes, int n_in,
                              void* d_out, int out_size) {
    const float* infer = (const float*)d_in[0];
    const float* ref   = (const float*)d_in[1];
    detail_kernel<<<NBLOCKS, WPB * 32>>>(infer, ref, (float*)d_out);
}

// round 11
// speedup vs baseline: 1.0716x; 1.0645x over previous
#include <cuda_runtime.h>

// Detail loss, simplified:
//   D = sum_c (infer - ref)   per image plane
//   out = (sum|D[w+1]-D[w-1]| + sum|D[h+1]-D[h-1]|) * 0.25 / (98*258*256)
// Warp-per-(8-row x 256-col) tile: lane owns 8 consecutive cols (2xfloat4 per
// plane per row) -> no column seam, horizontal neighbors via 2 shuffles.
// 3136 warps in ONE wave (regs capped 93 -> 22 warps/SM). Serpentine row walk
// so the 25% halo rows are L2 hits; DRAM stays at the 154MB mandatory floor.
// Single in-flight row buffer: combine(prev row) then immediately reissue the
// same registers for row g+2*dir.

#define NIMG   98            // 2*7*7
#define IMG_H  256
#define IMG_W  256
#define RSTRIP 8             // rows per warp tile
#define VSTRIPS (IMG_H / RSTRIP)         // 32
#define NWARPS (NIMG * VSTRIPS)          // 3136
#define WPB    2
#define NBLOCKS (NWARPS / WPB)           // 1568
#define PLANE  (IMG_H * IMG_W)

__device__ float        g_partials[NWARPS];
__device__ unsigned int g_count;     // zero-init; reset each launch by last block

struct Raw {
    float4 a[6];   // infer: 3 channels x 2 float4
    float4 b[6];   // ref
};

__device__ __forceinline__ void issue_load(const float* __restrict__ pi,
                                           const float* __restrict__ pr,
                                           int row, int lane, bool valid, Raw& r) {
    if (valid) {
        const size_t off = (size_t)row * IMG_W + lane * 8;
        #pragma unroll
        for (int c = 0; c < 3; c++) {
            const float* a = pi + (size_t)c * PLANE + off;
            const float* b = pr + (size_t)c * PLANE + off;
            r.a[c * 2]     = *(const float4*)a;
            r.a[c * 2 + 1] = *(const float4*)(a + 4);
            r.b[c * 2]     = *(const float4*)b;
            r.b[c * 2 + 1] = *(const float4*)(b + 4);
        }
    } else {
        const float4 z = make_float4(0.f, 0.f, 0.f, 0.f);
        #pragma unroll
        for (int i = 0; i < 6; i++) { r.a[i] = z; r.b[i] = z; }
    }
}

__device__ __forceinline__ void combine(const Raw& r, float d[8]) {
    #pragma unroll
    for (int j = 0; j < 8; j++) d[j] = 0.f;
    #pragma unroll
    for (int c = 0; c < 3; c++) {
        const float4 a0 = r.a[c * 2], a1 = r.a[c * 2 + 1];
        const float4 b0 = r.b[c * 2], b1 = r.b[c * 2 + 1];
        d[0] += a0.x - b0.x;  d[1] += a0.y - b0.y;
        d[2] += a0.z - b0.z;  d[3] += a0.w - b0.w;
        d[4] += a1.x - b1.x;  d[5] += a1.y - b1.y;
        d[6] += a1.z - b1.z;  d[7] += a1.w - b1.w;
    }
}

__global__ void __launch_bounds__(WPB * 32, 11)
detail_kernel(const float* __restrict__ infer, const float* __restrict__ ref,
              float* __restrict__ out) {
    const int tid   = threadIdx.x;
    const int lane  = tid & 31;
    const int gw    = blockIdx.x * WPB + (tid >> 5);   // global warp id
    const int n     = gw >> 5;                          // / VSTRIPS
    const int strip = gw & 31;
    const int r0    = strip * RSTRIP;

    // Serpentine: even strips walk top->bottom, odd strips bottom->top, so
    // rows shared across a strip boundary are read at the same time (L2 hit).
    const int dir    = (strip & 1) ? -1 : 1;
    const int gstart = (strip & 1) ? (r0 + RSTRIP - 1) : r0;

    const float* pi = infer + (size_t)n * 3 * PLANE;
    const float* pr = ref   + (size_t)n * 3 * PLANE;

    // Prologue: row gstart-dir -> pm, row gstart -> pc, row gstart+dir in buf.
    Raw buf, rtop, rcur;
    {
        const int rA = gstart - dir;
        issue_load(pi, pr, rA, lane, (unsigned)rA < IMG_H, rtop);
    }
    issue_load(pi, pr, gstart,       lane, true, rcur);
    issue_load(pi, pr, gstart + dir, lane, true, buf);

    float pm[8], pc[8], pn[8];        // rows g-dir, g, g+dir
    combine(rtop, pm);
    combine(rcur, pc);

    float sum = 0.f;

    #pragma unroll
    for (int h = 0; h < RSTRIP; h++) {
        const int g = gstart + h * dir;

        // Consume row g+dir (loads issued last iteration / prologue)...
        combine(buf, pn);
        // ...then immediately reissue the same registers for row g+2*dir.
        const int rnext = g + 2 * dir;
        issue_load(pi, pr, rnext, lane,
                   (h + 1 < RSTRIP) && ((unsigned)rnext < IMG_H), buf);

        // Horizontal gradient on row g (values in pc; 8 cols per lane).
        float l = __shfl_up_sync(0xffffffffu,  pc[7], 1);
        float r = __shfl_down_sync(0xffffffffu, pc[0], 1);
        if (lane == 0)  l = 0.f;   // image edge: zero padding
        if (lane == 31) r = 0.f;
        sum += fabsf(pc[1] - l);
        #pragma unroll
        for (int j = 1; j < 7; j++) sum += fabsf(pc[j + 1] - pc[j - 1]);
        sum += fabsf(r - pc[6]);

        // Vertical gradient: |D[g+1]-D[g-1]| = |pn-pm| for either direction.
        #pragma unroll
        for (int j = 0; j < 8; j++) sum += fabsf(pn[j] - pm[j]);

        // Roll the window.
        #pragma unroll
        for (int j = 0; j < 8; j++) { pm[j] = pc[j]; pc[j] = pn[j]; }
    }

    // Warp reduction.
    #pragma unroll
    for (int off = 16; off > 0; off >>= 1)
        sum += __shfl_down_sync(0xffffffffu, sum, off);

    __shared__ bool is_last;
    if (lane == 0) {
        g_partials[gw] = sum;
        __threadfence();
    }
    __syncthreads();
    if (tid == 0)
        is_last = (atomicAdd(&g_count, 1u) == NBLOCKS - 1);
    __syncthreads();

    if (is_last) {
        float t = 0.f;
        #pragma unroll 7
        for (int i = tid; i < NWARPS; i += WPB * 32)
            t += __ldcg(&g_partials[i]);
        #pragma unroll
        for (int off = 16; off > 0; off >>= 1)
            t += __shfl_down_sync(0xffffffffu, t, off);
        __shared__ float wsum[WPB];
        if (lane == 0) wsum[tid >> 5] = t;
        __syncthreads();
        if (tid == 0) {
            float u = 0.f;
            #pragma unroll
            for (int i = 0; i < WPB; i++) u += wsum[i];
            // 0.5 (gradient coeff) * 0.5 (avg of two losses) / (98*258*256)
            out[0] = u * (0.25f / 6472704.0f);
            g_count = 0;   // deterministic across graph replays
        }
    }
}

extern "C" void kernel_launch(void* const* d_in, const int* in_sizes, int n_in,
                              void* d_out, int out_size) {
    const float* infer = (const float*)d_in[0];
    const float* ref   = (const float*)d_in[1];
    detail_kernel<<<NBLOCKS, WPB * 32>>>(infer, ref, (float*)d_out);
}